// round 15
// baseline (speedup 1.0000x reference)
#include <cuda_runtime.h>

#define N_ROWS 32768
#define K_ANCH 32
#define D_FEAT 128

#define OPB     128                  // cohort blocks per branch
#define COHORT  (2 * OPB)            // 256 — all dispatched in wave 1
#define GX      (N_ROWS / 8)         // 4096 gather blocks per branch
#define GRID_X  (GX + COHORT)        // y==0 row hosts the cohort
#define ROWS_PB (N_ROWS / OPB)       // 256 rows per cohort block

// Scratch (zero at load; self-reset by globally-last block — replay-safe).
__device__ float g_xw[2][N_ROWS];
__device__ int   g_done[2];
__device__ int   g_fin;

// Scoped sync — NO gpu-scope fences (those emit CCTL.IVALL and flush L1D).
__device__ __forceinline__ int ld_acquire_gpu(const int* p) {
    int v;
    asm volatile("ld.acquire.gpu.global.b32 %0, [%1];" : "=r"(v) : "l"(p) : "memory");
    return v;
}
__device__ __forceinline__ void red_release_add(int* p, int v) {
    asm volatile("red.release.gpu.global.add.s32 [%0], %1;" :: "l"(p), "r"(v) : "memory");
}
__device__ __forceinline__ int atom_add_acq_rel(int* p, int v) {
    int old;
    asm volatile("atom.acq_rel.gpu.global.add.s32 %0, [%1], %2;"
                 : "=r"(old) : "l"(p), "r"(v) : "memory");
    return old;
}
// L2-coherent read of in-kernel-written data (NOT .nc — R11 lesson).
__device__ __forceinline__ float ld_cg(const float* p) {
    float v;
    asm volatile("ld.global.cg.f32 %0, [%1];" : "=f"(v) : "l"(p) : "memory");
    return v;
}

// One launch, grid (GRID_X, 2).
//  cohort  (y==0, x<COHORT): produce xw slice -> wait cohort -> emit op for 256 rows.
//  gather  (y==0, x>=COHORT -> branch0; y==1, x<GX -> branch1): pure gather, os only.
//  idle    (y==1, x>=GX): only participate in the finish counter.
__global__ __launch_bounds__(256) void fused_kernel(
    const float* __restrict__ x1, const int* __restrict__ idx1, const float* __restrict__ dm1,
    const float* __restrict__ x2, const int* __restrict__ idx2, const float* __restrict__ dm2,
    const float* __restrict__ w,  const float* __restrict__ b_out,
    float* __restrict__ op1, float* __restrict__ os1,
    float* __restrict__ op2, float* __restrict__ os2)
{
    const int tid = threadIdx.x;

    if (blockIdx.y == 0 && blockIdx.x < COHORT) {
        // ======================= cohort block =======================
        const int br = (blockIdx.x >= OPB) ? 1 : 0;
        const int cc = blockIdx.x - br * OPB;
        const float* __restrict__ x   = br ? x2   : x1;
        const int*   __restrict__ idx = br ? idx2 : idx1;
        const float* __restrict__ dm  = br ? dm2  : dm1;
        float*       __restrict__ op  = br ? op2  : op1;

        const int warp = tid >> 5;
        const int lane = tid & 31;

        // --- produce xw slice: rows [cc*ROWS_PB, cc*ROWS_PB + ROWS_PB) ---
        {
            const float4 wv = reinterpret_cast<const float4*>(w)[lane];
            const int base = cc * ROWS_PB + warp * (ROWS_PB / 8);
            #pragma unroll 4
            for (int i = 0; i < ROWS_PB / 8; i++) {
                const int row = base + i;
                const float4 xv =
                    reinterpret_cast<const float4*>(x)[row * (D_FEAT / 4) + lane];
                float s = xv.x * wv.x + xv.y * wv.y + xv.z * wv.z + xv.w * wv.w;
                #pragma unroll
                for (int off = 16; off > 0; off >>= 1)
                    s += __shfl_xor_sync(0xFFFFFFFFu, s, off);
                if (lane == 0) g_xw[br][row] = s;
            }
        }
        __syncthreads();
        if (tid == 0) red_release_add(&g_done[br], 1);   // publish slice

        // --- wait for this branch's whole table (cohort-only wait) ---
        if (tid == 0) {
            int spins = 0;
            while (ld_acquire_gpu(&g_done[br]) < OPB) {
                if (++spins > 4) __nanosleep(128);
            }
        }
        __syncthreads();

        // --- emit op for the same 256 rows: 8192 elements, 32 iters ---
        const float b0 = __ldg(&b_out[0]);
        const int elem_base = cc * ROWS_PB * K_ANCH;     // linear into [N,K]
        #pragma unroll 4
        for (int it = 0; it < (ROWS_PB * K_ANCH) / 256; it++) {
            const int e = elem_base + it * 256 + tid;    // coalesced
            const int   a = idx[e];
            const float d = dm [e];
            op[e] = fmaf(d, ld_cg(&g_xw[br][a]), b0);
        }
    } else if (blockIdx.y == 1 && blockIdx.x >= GX) {
        // idle filler block — falls through to finish counter only
    } else {
        // ======================= gather block =======================
        const int br = blockIdx.y;
        const int bx = br ? blockIdx.x : (blockIdx.x - COHORT);
        const float* __restrict__ x   = br ? x2   : x1;
        const int*   __restrict__ idx = br ? idx2 : idx1;
        const float* __restrict__ dm  = br ? dm2  : dm1;
        float*       __restrict__ os  = br ? os2  : os1;

        const int warp = tid >> 5;
        const int lane = tid & 31;
        const int n    = bx * 8 + warp;

        __shared__ int4 s_meta[8][16];   // (off_2p, dm_2p, off_2p+1, dm_2p+1)

        const int   a = idx[n * K_ANCH + lane];    // coalesced
        const float d = dm [n * K_ANCH + lane];    // coalesced
        {
            int2* dst = reinterpret_cast<int2*>(&s_meta[warp][0]) + lane;
            *dst = make_int2(a * (int)(D_FEAT * sizeof(float)), __float_as_int(d));
        }
        __syncwarp();

        const char* __restrict__ xb = reinterpret_cast<const char*>(x);
        const int lane_byte = lane * 16;

        float4 acc = make_float4(0.f, 0.f, 0.f, 0.f);

        #pragma unroll
        for (int p = 0; p < 16; p++) {
            const int4 m = s_meta[warp][p];          // broadcast LDS.128
            const float d0 = __int_as_float(m.y);
            const float d1 = __int_as_float(m.w);
            const float4 v0 = __ldg(reinterpret_cast<const float4*>(xb + m.x + lane_byte));
            const float4 v1 = __ldg(reinterpret_cast<const float4*>(xb + m.z + lane_byte));
            acc.x = fmaf(d0, v0.x, acc.x);
            acc.y = fmaf(d0, v0.y, acc.y);
            acc.z = fmaf(d0, v0.z, acc.z);
            acc.w = fmaf(d0, v0.w, acc.w);
            acc.x = fmaf(d1, v1.x, acc.x);
            acc.y = fmaf(d1, v1.y, acc.y);
            acc.z = fmaf(d1, v1.z, acc.z);
            acc.w = fmaf(d1, v1.w, acc.w);
        }

        const float inv = 1.0f / (float)K_ANCH;
        acc.x *= inv; acc.y *= inv; acc.z *= inv; acc.w *= inv;
        reinterpret_cast<float4*>(os)[n * (D_FEAT / 4) + lane] = acc;  // coalesced
    }

    // ---------- self-reset of counters by the globally-last block ----------
    if (tid == 0) {
        const int total = (int)(gridDim.x * gridDim.y);
        if (atom_add_acq_rel(&g_fin, 1) == total - 1) {
            g_done[0] = 0;
            g_done[1] = 0;
            g_fin     = 0;
        }
    }
}

extern "C" void kernel_launch(void* const* d_in, const int* in_sizes, int n_in,
                              void* d_out, int out_size) {
    const float* x1   = (const float*)d_in[0];
    const int*   idx1 = (const int*)  d_in[1];
    const float* dm1  = (const float*)d_in[2];
    const float* x2   = (const float*)d_in[3];
    const int*   idx2 = (const int*)  d_in[4];
    const float* dm2  = (const float*)d_in[5];
    const float* w    = (const float*)d_in[6];
    const float* b    = (const float*)d_in[7];

    float* out = (float*)d_out;
    float* op1 = out;                                       // [N, K]
    float* os1 = op1 + (size_t)N_ROWS * K_ANCH;             // [N, D]
    float* op2 = os1 + (size_t)N_ROWS * D_FEAT;             // [N, K]
    float* os2 = op2 + (size_t)N_ROWS * K_ANCH;             // [N, D]

    dim3 gg(GRID_X, 2);
    fused_kernel<<<gg, 256>>>(x1, idx1, dm1, x2, idx2, dm2, w, b,
                              op1, os1, op2, os2);
}